// round 15
// baseline (speedup 1.0000x reference)
#include <cuda_runtime.h>
#include <cuda_fp16.h>
#include <math.h>
#include <stdint.h>

#define NN   50000
#define EE   400000
#define ET   (EE + NN)
#define F    256
#define HH   4
#define CC   64
#define GG   64
#define NCLS 10

// ---------------- scratch (static device globals; no allocations) -----------
__device__ __align__(16) __half g_hh[(size_t)NN * F];    // h = A' @ W, fp16
__device__ __align__(16) __half g_y1h[(size_t)NN * F];   // layer-1 output, fp16
__device__ float g_asrc[NN * HH];
__device__ float g_adst[NN * HH];
__device__ float g_sum[F], g_sumsq[F];
__device__ float g_sc1[F], g_sh1[F];
__device__ float g_sc2[F], g_sh2[F];
__device__ float g_pool[GG * F];
__device__ float g_cnt[GG];
__device__ __align__(16) __half g_Bp[256 * 256];   // fp16 W
// CSR
__device__ int   g_cnt_n[NN];
__device__ int   g_rp[NN + 1];
__device__ int   g_col[ET];
#define SCAN_NB ((NN + 255) / 256)
__device__ int   g_blk[256];

// ---------------- helpers -----------------------------------------------------
__device__ __forceinline__ uint32_t pack_h2(float a, float b) {
    __half2 h = __floats2half2_rn(a, b);
    return *(uint32_t*)&h;
}
__device__ __forceinline__ void red4(float* p, float a, float b, float c, float d) {
    asm volatile("red.global.add.v4.f32 [%0], {%1,%2,%3,%4};"
                 :: "l"(p), "f"(a), "f"(b), "f"(c), "f"(d) : "memory");
}

// ---- conv_B: W[256][256] fp32 -> fp16 ---------------------------------------
__global__ void conv_B(const float* __restrict__ W) {
    int k = blockIdx.x, n = threadIdx.x;
    g_Bp[(size_t)k * 256 + n] = __float2half_rn(W[k * 256 + n]);
}

// ============ fp16 mma.sync GEMM, K=256, inline convert, fused attn ==========
#define PA 80
#define PB 272
#define ABUF (128 * PA)
#define BBUF (32 * PB)
#define STG  (ABUF + BBUF)

__device__ __forceinline__ uint32_t smem_u32(const void* p) {
    uint32_t a;
    asm("{ .reg .u64 t; cvta.to.shared.u64 t, %1; cvt.u32.u64 %0, t; }"
        : "=r"(a) : "l"(p));
    return a;
}
__device__ __forceinline__ void ldsm_x4(uint32_t* a, uint32_t addr) {
    asm volatile("ldmatrix.sync.aligned.m8n8.x4.shared.b16 {%0,%1,%2,%3}, [%4];"
                 : "=r"(a[0]), "=r"(a[1]), "=r"(a[2]), "=r"(a[3]) : "r"(addr));
}
__device__ __forceinline__ void ldsm_x2t(uint32_t* b, uint32_t addr) {
    asm volatile("ldmatrix.sync.aligned.m8n8.x2.trans.shared.b16 {%0,%1}, [%2];"
                 : "=r"(b[0]), "=r"(b[1]) : "r"(addr));
}
__device__ __forceinline__ void mma16816(float* d, const uint32_t* a,
                                         const uint32_t* b) {
    asm volatile(
        "mma.sync.aligned.m16n8k16.row.col.f32.f16.f16.f32 "
        "{%0,%1,%2,%3}, {%4,%5,%6,%7}, {%8,%9}, {%0,%1,%2,%3};"
        : "+f"(d[0]), "+f"(d[1]), "+f"(d[2]), "+f"(d[3])
        : "r"(a[0]), "r"(a[1]), "r"(a[2]), "r"(a[3]), "r"(b[0]), "r"(b[1]));
}
__device__ __forceinline__ void load_conv(const float* agp32, const __half* agp16,
                                          int kbase,
                                          const float* scale, const float* shift,
                                          bool ok, int sidx, uint32_t* hp) {
    float e[16];
    if (ok) {
        if (agp16) {
            uint4 v0 = *(const uint4*)(agp16 + kbase);
            uint4 v1 = *(const uint4*)(agp16 + kbase + 8);
            uint32_t u[4] = {v0.x, v0.y, v0.z, v0.w};
            uint32_t w[4] = {v1.x, v1.y, v1.z, v1.w};
#pragma unroll
            for (int i = 0; i < 4; i++) {
                float2 f = __half22float2(*(__half2*)&u[i]);
                e[i * 2 + 0] = f.x; e[i * 2 + 1] = f.y;
                float2 g = __half22float2(*(__half2*)&w[i]);
                e[8 + i * 2 + 0] = g.x; e[8 + i * 2 + 1] = g.y;
            }
        } else {
#pragma unroll
            for (int i = 0; i < 4; i++) {
                float4 v = *(const float4*)(agp32 + kbase + i * 4);
                e[i * 4 + 0] = v.x; e[i * 4 + 1] = v.y;
                e[i * 4 + 2] = v.z; e[i * 4 + 3] = v.w;
            }
        }
        if (scale) {
#pragma unroll
            for (int i = 0; i < 16; i++)
                e[i] = e[i] * scale[sidx + i] + shift[sidx + i];
        }
    } else {
#pragma unroll
        for (int i = 0; i < 16; i++) e[i] = 0.f;
    }
#pragma unroll
    for (int p = 0; p < 8; p++) hp[p] = pack_h2(e[2 * p], e[2 * p + 1]);
}

__global__ __launch_bounds__(256, 2)
void gemm_fp16(const float* __restrict__ A, const __half* __restrict__ A16,
               __half* __restrict__ C, int M,
               const float* __restrict__ scale, const float* __restrict__ shift,
               const float* __restrict__ atts, const float* __restrict__ attd) {
    __shared__ __align__(16) char sm[2 * STG];
    const int t = threadIdx.x, lane = t & 31, w = t >> 5;
    const int wm = w & 1, wn = w >> 1;
    const int row0 = blockIdx.x * 128, col0 = blockIdx.y * 128;
    const uint32_t sb = smem_u32(sm);

    float acc[4][4][4];
#pragma unroll
    for (int i = 0; i < 4; i++)
#pragma unroll
        for (int j = 0; j < 4; j++)
#pragma unroll
            for (int k = 0; k < 4; k++) acc[i][j][k] = 0.f;

    const int ar = t >> 1, apart = t & 1;
    const bool a_ok = (row0 + ar) < M;
    const float* agp32 = A   ? A   + (size_t)(row0 + ar) * 256 + apart * 16 : NULL;
    const __half* agp16 = A16 ? A16 + (size_t)(row0 + ar) * 256 + apart * 16 : NULL;
    const int br = t >> 3, bseg = t & 7;
    const __half* bgp = g_Bp + (size_t)br * 256 + col0 + bseg * 16;

    uint32_t hp[8];

    load_conv(agp32, agp16, 0, scale, shift, a_ok, apart * 16, hp);
    {
        char* pa = sm + ar * PA + apart * 32;
        *(uint4*)pa = *(uint4*)&hp[0];
        *(uint4*)(pa + 16) = *(uint4*)&hp[4];
        uint4 lb0 = *(const uint4*)(bgp);
        uint4 lb1 = *(const uint4*)(bgp + 8);
        char* pb = sm + ABUF + br * PB + bseg * 32;
        *(uint4*)pb = lb0; *(uint4*)(pb + 16) = lb1;
    }
    __syncthreads();

    for (int s = 0; s < 8; s++) {
        const int buf = s & 1;
        const uint32_t sba = sb + buf * STG;
        const int sn = s + 1;
        uint4 lb0, lb1;
        if (s < 7) {
            lb0 = *(const uint4*)(bgp + (size_t)(sn * 32) * 256);
            lb1 = *(const uint4*)(bgp + (size_t)(sn * 32) * 256 + 8);
            load_conv(agp32, agp16, sn * 32, scale, shift, a_ok,
                      sn * 32 + apart * 16, hp);
        }
#pragma unroll
        for (int kh = 0; kh < 2; kh++) {
            uint32_t afr[4][4], bfr[4][2];
#pragma unroll
            for (int mi = 0; mi < 4; mi++) {
                uint32_t addr = sba + (uint32_t)(wm * 64 + mi * 16 + (lane & 15)) * PA
                              + kh * 32 + (lane >> 4) * 16;
                ldsm_x4(afr[mi], addr);
            }
#pragma unroll
            for (int nf = 0; nf < 4; nf++) {
                uint32_t addr = sba + ABUF + (uint32_t)(kh * 16 + (lane & 15)) * PB
                              + (wn * 32 + nf * 8) * 2;
                ldsm_x2t(bfr[nf], addr);
            }
#pragma unroll
            for (int mi = 0; mi < 4; mi++)
#pragma unroll
                for (int nf = 0; nf < 4; nf++)
                    mma16816(acc[mi][nf], afr[mi], bfr[nf]);
        }
        if (s < 7) {
            char* base = sm + (buf ^ 1) * STG;
            char* pb = base + ABUF + br * PB + bseg * 32;
            *(uint4*)pb = lb0; *(uint4*)(pb + 16) = lb1;
            char* pa = base + ar * PA + apart * 32;
            *(uint4*)pa = *(uint4*)&hp[0];
            *(uint4*)(pa + 16) = *(uint4*)&hp[4];
        }
        __syncthreads();
    }

    // ---- epilogue: store C (fp16), per-warp att partials -> smem, combine ---
    float* part = (float*)sm;
#pragma unroll
    for (int mi = 0; mi < 4; mi++) {
        int lr_lo = wm * 64 + mi * 16 + (lane >> 2);
        int lr_hi = lr_lo + 8;
        int r_lo = row0 + lr_lo, r_hi = row0 + lr_hi;
        float ds0 = 0.f, dd0 = 0.f, ds1 = 0.f, dd1 = 0.f;
#pragma unroll
        for (int nf = 0; nf < 4; nf++) {
            int c = col0 + wn * 32 + nf * 8 + (lane & 3) * 2;
            float v0 = acc[mi][nf][0], v1 = acc[mi][nf][1];
            float v2 = acc[mi][nf][2], v3 = acc[mi][nf][3];
            if (r_lo < M) *(__half2*)(C + (size_t)r_lo * 256 + c) = __floats2half2_rn(v0, v1);
            if (r_hi < M) *(__half2*)(C + (size_t)r_hi * 256 + c) = __floats2half2_rn(v2, v3);
            float s0 = atts[c], s1 = atts[c + 1];
            float d0 = attd[c], d1 = attd[c + 1];
            ds0 += v0 * s0 + v1 * s1; dd0 += v0 * d0 + v1 * d1;
            ds1 += v2 * s0 + v3 * s1; dd1 += v2 * d0 + v3 * d1;
        }
#pragma unroll
        for (int o = 1; o <= 2; o <<= 1) {
            ds0 += __shfl_xor_sync(0xFFFFFFFFu, ds0, o);
            dd0 += __shfl_xor_sync(0xFFFFFFFFu, dd0, o);
            ds1 += __shfl_xor_sync(0xFFFFFFFFu, ds1, o);
            dd1 += __shfl_xor_sync(0xFFFFFFFFu, dd1, o);
        }
        if ((lane & 3) == 0) {
            part[(lr_lo * 4 + wn) * 2 + 0] = ds0;
            part[(lr_lo * 4 + wn) * 2 + 1] = dd0;
            part[(lr_hi * 4 + wn) * 2 + 0] = ds1;
            part[(lr_hi * 4 + wn) * 2 + 1] = dd1;
        }
    }
    __syncthreads();
    {
        int lr = t & 127, sd = t >> 7;
        int gr = row0 + lr;
        if (gr < M) {
            float* dst = sd ? g_adst : g_asrc;
#pragma unroll
            for (int hl = 0; hl < 2; hl++) {
                float v = part[(lr * 4 + 2 * hl) * 2 + sd]
                        + part[(lr * 4 + 2 * hl + 1) * 2 + sd];
                dst[gr * HH + (col0 >> 6) + hl] = v;
            }
        }
    }
}

// ------------------------------ CSR build -----------------------------------
__global__ void csr_zero() {
    int i = blockIdx.x * blockDim.x + threadIdx.x;
    if (i < NN) g_cnt_n[i] = 0;
    if (i < F)  { g_sum[i] = 0.f; g_sumsq[i] = 0.f; }
    if (i < GG * F) g_pool[i] = 0.f;
    if (i < GG) g_cnt[i] = 0.f;
}
__global__ void csr_hist(const int* __restrict__ ei) {
    int e = blockIdx.x * blockDim.x + threadIdx.x;
    if (e >= ET) return;
    int d = (e < EE) ? ei[EE + e] : e - EE;
    atomicAdd(&g_cnt_n[d], 1);
}
__global__ void cnt_hist(const int* __restrict__ bt) {
    __shared__ int hcnt[GG];
    int t = threadIdx.x;
    if (t < GG) hcnt[t] = 0;
    __syncthreads();
    int i = blockIdx.x * blockDim.x + t;
    if (i < NN) atomicAdd(&hcnt[bt[i]], 1);
    __syncthreads();
    if (t < GG && hcnt[t]) atomicAdd(&g_cnt[t], (float)hcnt[t]);
}
__global__ void scan_p1() {
    __shared__ int ps[256];
    int t = threadIdx.x, i = blockIdx.x * 256 + t;
    int v = (i < NN) ? g_cnt_n[i] : 0;
    ps[t] = v;
    __syncthreads();
#pragma unroll
    for (int off = 128; off; off >>= 1) {
        if (t < off) ps[t] += ps[t + off];
        __syncthreads();
    }
    if (t == 0) g_blk[blockIdx.x] = ps[0];
}
__global__ void scan_p2() {
    __shared__ int ps[256];
    int t = threadIdx.x;
    ps[t] = (t < SCAN_NB) ? g_blk[t] : 0;
    __syncthreads();
#pragma unroll
    for (int off = 1; off < 256; off <<= 1) {
        int v = (t >= off) ? ps[t - off] : 0;
        __syncthreads();
        ps[t] += v;
        __syncthreads();
    }
    g_blk[t] = ps[t];
}
__global__ void scan_p3() {
    __shared__ int ps[256];
    int t = threadIdx.x, b = blockIdx.x, i = b * 256 + t;
    int v = (i < NN) ? g_cnt_n[i] : 0;
    ps[t] = v;
    __syncthreads();
#pragma unroll
    for (int off = 1; off < 256; off <<= 1) {
        int u = (t >= off) ? ps[t - off] : 0;
        __syncthreads();
        ps[t] += u;
        __syncthreads();
    }
    int base = b ? g_blk[b - 1] : 0;
    int excl = base + ps[t] - v;
    if (i < NN) {
        g_rp[i] = excl;
        g_cnt_n[i] = excl;
        if (i == NN - 1) g_rp[NN] = excl + v;
    }
}
__global__ void csr_scatter(const int* __restrict__ ei) {
    int e = blockIdx.x * blockDim.x + threadIdx.x;
    if (e >= ET) return;
    int s, d;
    if (e < EE) { s = ei[e]; d = ei[EE + e]; }
    else        { s = d = e - EE; }
    int pos = atomicAdd(&g_cnt_n[d], 1);
    g_col[pos] = s;
}

// ----- fused GAT aggregate: ONE warp per dst row (lane = 8 cols, 16B loads) --
#define RPW 4
__global__ __launch_bounds__(256)
void gat_agg(const float* __restrict__ b,
             const float* __restrict__ xin32,
             const __half* __restrict__ xin16,
             const float* __restrict__ rscale,
             const float* __restrict__ rshift,
             __half* __restrict__ y16,
             const int* __restrict__ bat, int do_pool) {
    __shared__ float bsum[F], bsq[F];
    int t = threadIdx.x;
    bsum[t] = 0.f; bsq[t] = 0.f;
    __syncthreads();

    int lane = t & 31;
    int gwarp = blockIdx.x * 8 + (t >> 5);
    int d0 = gwarp * RPW;
    int c = lane << 3;            // 8 cols per lane
    int h = lane >> 3;            // head

    float bias[8], sc[8], sh[8];
    {
        float4 b0 = *(const float4*)(b + c);
        float4 b1 = *(const float4*)(b + c + 4);
        bias[0]=b0.x; bias[1]=b0.y; bias[2]=b0.z; bias[3]=b0.w;
        bias[4]=b1.x; bias[5]=b1.y; bias[6]=b1.z; bias[7]=b1.w;
#pragma unroll
        for (int j = 0; j < 8; j++) {
            sc[j] = rscale ? rscale[c + j] : 1.f;
            sh[j] = rshift ? rshift[c + j] : 0.f;
        }
    }

    float ss[8] = {0,0,0,0,0,0,0,0};
    float sq[8] = {0,0,0,0,0,0,0,0};
    float pa[8] = {0,0,0,0,0,0,0,0};
    int curg = -1;

#pragma unroll
    for (int rr = 0; rr < RPW; rr++) {
        int d = d0 + rr;
        if (d >= NN) break;
        float ad = g_adst[d * HH + h];
        float acc[8] = {0,0,0,0,0,0,0,0};
        float den = 0.f;
        int e0 = g_rp[d], e1 = g_rp[d + 1];
        int e = e0;
        // 8-wide pipelined leg
        for (; e + 8 <= e1; e += 8) {
            int sid[8];
#pragma unroll
            for (int j = 0; j < 8; j++) sid[j] = g_col[e + j];
            float av[8];
            uint4 uv[8];
#pragma unroll
            for (int j = 0; j < 8; j++) av[j] = g_asrc[sid[j] * HH + h];
#pragma unroll
            for (int j = 0; j < 8; j++)
                uv[j] = *(const uint4*)(g_hh + (size_t)sid[j] * F + c);
#pragma unroll
            for (int j = 0; j < 8; j++) {
                float v = av[j] + ad;
                v = v > 0.f ? v : 0.2f * v;
                float ex = __expf(v);
                den += ex;
                float2 f0 = __half22float2(*(__half2*)&uv[j].x);
                float2 f1 = __half22float2(*(__half2*)&uv[j].y);
                float2 f2 = __half22float2(*(__half2*)&uv[j].z);
                float2 f3 = __half22float2(*(__half2*)&uv[j].w);
                acc[0] += ex * f0.x; acc[1] += ex * f0.y;
                acc[2] += ex * f1.x; acc[3] += ex * f1.y;
                acc[4] += ex * f2.x; acc[5] += ex * f2.y;
                acc[6] += ex * f3.x; acc[7] += ex * f3.y;
            }
        }
        // 4-wide leg
        for (; e + 4 <= e1; e += 4) {
            int sid[4];
#pragma unroll
            for (int j = 0; j < 4; j++) sid[j] = g_col[e + j];
            float av[4];
            uint4 uv[4];
#pragma unroll
            for (int j = 0; j < 4; j++) av[j] = g_asrc[sid[j] * HH + h];
#pragma unroll
            for (int j = 0; j < 4; j++)
                uv[j] = *(const uint4*)(g_hh + (size_t)sid[j] * F + c);
#pragma unroll
            for (int j = 0; j < 4; j++) {
                float v = av[j] + ad;
                v = v > 0.f ? v : 0.2f * v;
                float ex = __expf(v);
                den += ex;
                float2 f0 = __half22float2(*(__half2*)&uv[j].x);
                float2 f1 = __half22float2(*(__half2*)&uv[j].y);
                float2 f2 = __half22float2(*(__half2*)&uv[j].z);
                float2 f3 = __half22float2(*(__half2*)&uv[j].w);
                acc[0] += ex * f0.x; acc[1] += ex * f0.y;
                acc[2] += ex * f1.x; acc[3] += ex * f1.y;
                acc[4] += ex * f2.x; acc[5] += ex * f2.y;
                acc[6] += ex * f3.x; acc[7] += ex * f3.y;
            }
        }
        for (; e < e1; e++) {
            int s = g_col[e];
            float v = g_asrc[s * HH + h] + ad;
            v = v > 0.f ? v : 0.2f * v;
            float ex = __expf(v);
            den += ex;
            uint4 u = *(const uint4*)(g_hh + (size_t)s * F + c);
            float2 f0 = __half22float2(*(__half2*)&u.x);
            float2 f1 = __half22float2(*(__half2*)&u.y);
            float2 f2 = __half22float2(*(__half2*)&u.z);
            float2 f3 = __half22float2(*(__half2*)&u.w);
            acc[0] += ex * f0.x; acc[1] += ex * f0.y;
            acc[2] += ex * f1.x; acc[3] += ex * f1.y;
            acc[4] += ex * f2.x; acc[5] += ex * f2.y;
            acc[6] += ex * f3.x; acc[7] += ex * f3.y;
        }
        float inv = __fdividef(1.f, den);
        float xv[8];
        if (xin16) {
            uint4 u = *(const uint4*)(xin16 + (size_t)d * F + c);
            float2 f0 = __half22float2(*(__half2*)&u.x);
            float2 f1 = __half22float2(*(__half2*)&u.y);
            float2 f2 = __half22float2(*(__half2*)&u.z);
            float2 f3 = __half22float2(*(__half2*)&u.w);
            xv[0]=f0.x; xv[1]=f0.y; xv[2]=f1.x; xv[3]=f1.y;
            xv[4]=f2.x; xv[5]=f2.y; xv[6]=f3.x; xv[7]=f3.y;
        } else {
            float4 x0 = *(const float4*)(xin32 + (size_t)d * F + c);
            float4 x1 = *(const float4*)(xin32 + (size_t)d * F + c + 4);
            xv[0]=x0.x; xv[1]=x0.y; xv[2]=x0.z; xv[3]=x0.w;
            xv[4]=x1.x; xv[5]=x1.y; xv[6]=x1.z; xv[7]=x1.w;
        }
        float o[8];
#pragma unroll
        for (int j = 0; j < 8; j++) {
            float v = acc[j] * inv + bias[j];
            v = v > 0.f ? v : expm1f(v);
            o[j] = v + xv[j] * sc[j] + sh[j];
        }
        if (do_pool) {
            int gb = bat[d];
            if (gb != curg) {
                if (curg >= 0) {
                    red4(&g_pool[curg * F + c],     pa[0], pa[1], pa[2], pa[3]);
                    red4(&g_pool[curg * F + c + 4], pa[4], pa[5], pa[6], pa[7]);
                }
                curg = gb;
#pragma unroll
                for (int j = 0; j < 8; j++) pa[j] = 0.f;
            }
#pragma unroll
            for (int j = 0; j < 8; j++) pa[j] += o[j];
        } else {
            __half2 h0 = __floats2half2_rn(o[0], o[1]);
            __half2 h1 = __floats2half2_rn(o[2], o[3]);
            __half2 h2 = __floats2half2_rn(o[4], o[5]);
            __half2 h3 = __floats2half2_rn(o[6], o[7]);
            uint4 uo;
            uo.x = *(uint32_t*)&h0; uo.y = *(uint32_t*)&h1;
            uo.z = *(uint32_t*)&h2; uo.w = *(uint32_t*)&h3;
            *(uint4*)(y16 + (size_t)d * F + c) = uo;
        }
#pragma unroll
        for (int j = 0; j < 8; j++) { ss[j] += o[j]; sq[j] += o[j] * o[j]; }
    }
    if (do_pool && curg >= 0) {
        red4(&g_pool[curg * F + c],     pa[0], pa[1], pa[2], pa[3]);
        red4(&g_pool[curg * F + c + 4], pa[4], pa[5], pa[6], pa[7]);
    }
#pragma unroll
    for (int j = 0; j < 8; j++) {
        atomicAdd(&bsum[c + j], ss[j]);
        atomicAdd(&bsq[c + j],  sq[j]);
    }
    __syncthreads();
    atomicAdd(&g_sum[t],   bsum[t]);
    atomicAdd(&g_sumsq[t], bsq[t]);
}

__global__ void bn_final(const float* __restrict__ gm, const float* __restrict__ bt,
                         float* __restrict__ sc_out, float* __restrict__ sh_out) {
    int f = threadIdx.x;
    float mu  = g_sum[f] / (float)NN;
    float var = g_sumsq[f] / (float)NN - mu * mu;
    float sc  = gm[f] * rsqrtf(var + 1e-5f);
    sc_out[f] = sc;
    sh_out[f] = bt[f] - mu * sc;
    g_sum[f] = 0.f; g_sumsq[f] = 0.f;
}

// ---------- MLP head: BN2 affine on pooled raw sums + log softmax ------------
__global__ void mlp_head(const float* __restrict__ fc1w, const float* __restrict__ fc1b,
                         const float* __restrict__ fc2w, const float* __restrict__ fc2b,
                         float* __restrict__ out) {
    __shared__ float p[F];
    __shared__ float z[CC];
    __shared__ float l[NCLS];
    __shared__ float red[2];
    int g = blockIdx.x;
    int t = threadIdx.x;
    float cnt = fmaxf(g_cnt[g], 1.f);
    float inv = 1.f / cnt;
    for (int k = t; k < F; k += 64)
        p[k] = (g_sc2[k] * g_pool[g * F + k] + g_sh2[k] * cnt) * inv;
    __syncthreads();
    float acc = fc1b[t];
    for (int k = 0; k < F; k++) acc += p[k] * fc1w[k * CC + t];
    z[t] = fmaxf(acc, 0.f);
    __syncthreads();
    if (t < NCLS) {
        float a = fc2b[t];
        for (int k = 0; k < CC; k++) a += z[k] * fc2w[k * NCLS + t];
        l[t] = a;
    }
    __syncthreads();
    if (t == 0) {
        float m = l[0];
        for (int i = 1; i < NCLS; i++) m = fmaxf(m, l[i]);
        float s = 0.f;
        for (int i = 0; i < NCLS; i++) s += expf(l[i] - m);
        red[0] = m; red[1] = logf(s);
    }
    __syncthreads();
    if (t < NCLS) out[g * NCLS + t] = l[t] - red[0] - red[1];
}

// ---------------------------------- launch ----------------------------------
extern "C" void kernel_launch(void* const* d_in, const int* in_sizes, int n_in,
                              void* d_out, int out_size) {
    const float* x    = (const float*)d_in[0];
    const int*   ei   = (const int*)  d_in[1];
    const int*   bat  = (const int*)  d_in[2];
    const float* W1   = (const float*)d_in[3];
    const float* as1  = (const float*)d_in[4];
    const float* ad1  = (const float*)d_in[5];
    const float* b1   = (const float*)d_in[6];
    const float* gm1  = (const float*)d_in[7];
    const float* be1  = (const float*)d_in[8];
    const float* W2   = (const float*)d_in[9];
    const float* as2  = (const float*)d_in[10];
    const float* ad2  = (const float*)d_in[11];
    const float* b2   = (const float*)d_in[12];
    const float* gm2  = (const float*)d_in[13];
    const float* be2  = (const float*)d_in[14];
    const float* fc1w = (const float*)d_in[15];
    const float* fc1b = (const float*)d_in[16];
    const float* fc2w = (const float*)d_in[17];
    const float* fc2b = (const float*)d_in[18];
    float* out = (float*)d_out;

    __half *phh, *py1h;
    float *psc1, *psh1, *psc2, *psh2;
    cudaGetSymbolAddress((void**)&phh,  g_hh);
    cudaGetSymbolAddress((void**)&py1h, g_y1h);
    cudaGetSymbolAddress((void**)&psc1, g_sc1);
    cudaGetSymbolAddress((void**)&psh1, g_sh1);
    cudaGetSymbolAddress((void**)&psc2, g_sc2);
    cudaGetSymbolAddress((void**)&psh2, g_sh2);

    static cudaStream_t s2 = nullptr;
    static cudaEvent_t evFork = nullptr, evCsr = nullptr,
                       evGemm1 = nullptr, evConvB2 = nullptr;
    if (!s2) {
        cudaStreamCreateWithFlags(&s2, cudaStreamNonBlocking);
        cudaEventCreateWithFlags(&evFork,   cudaEventDisableTiming);
        cudaEventCreateWithFlags(&evCsr,    cudaEventDisableTiming);
        cudaEventCreateWithFlags(&evGemm1,  cudaEventDisableTiming);
        cudaEventCreateWithFlags(&evConvB2, cudaEventDisableTiming);
    }

    const int TPB = 256;
    const int nET = (ET + TPB - 1) / TPB;
    const int nNN = (NN + TPB - 1) / TPB;
    dim3 mmGrid((NN + 127) / 128, 2);
    const int nAGG  = (NN + 8 * RPW - 1) / (8 * RPW);
    const int nZERO = (GG * F + TPB - 1) / TPB > nNN
                      ? (GG * F + TPB - 1) / TPB : nNN;

    // ---- fork: CSR build chain on side stream, GEMM path on main -----------
    cudaEventRecord(evFork, 0);
    cudaStreamWaitEvent(s2, evFork, 0);

    csr_zero<<<nZERO, TPB, 0, s2>>>();
    csr_hist<<<nET, TPB, 0, s2>>>(ei);
    cnt_hist<<<nNN, TPB, 0, s2>>>(bat);
    scan_p1<<<SCAN_NB, 256, 0, s2>>>();
    scan_p2<<<1, 256, 0, s2>>>();
    scan_p3<<<SCAN_NB, 256, 0, s2>>>();
    csr_scatter<<<nET, TPB, 0, s2>>>(ei);
    cudaEventRecord(evCsr, s2);

    // main: layer-1 GEMM (independent of CSR)
    conv_B<<<256, 256>>>(W1);
    gemm_fp16<<<mmGrid, 256>>>(x, NULL, phh, NN, NULL, NULL, as1, ad1);
    cudaEventRecord(evGemm1, 0);

    // side: conv_B(W2) after gemm1 released g_Bp, overlapping gat_agg1
    cudaStreamWaitEvent(s2, evGemm1, 0);
    conv_B<<<256, 256, 0, s2>>>(W2);
    cudaEventRecord(evConvB2, s2);

    // main: join CSR, run layer-1 aggregation (writes y1 fp16)
    cudaStreamWaitEvent(0, evCsr, 0);
    gat_agg<<<nAGG, 256>>>(b1, x, NULL, NULL, NULL, py1h, bat, 0);
    bn_final<<<1, F>>>(gm1, be1, psc1, psh1);

    // main: join conv_B(W2), layer 2 (A from fp16 y1, pooling fused)
    cudaStreamWaitEvent(0, evConvB2, 0);
    gemm_fp16<<<mmGrid, 256>>>(NULL, py1h, phh, NN, psc1, psh1, as2, ad2);
    gat_agg<<<nAGG, 256>>>(b2, NULL, py1h, psc1, psh1, NULL, bat, 1);
    bn_final<<<1, F>>>(gm2, be2, psc2, psh2);

    // ---- head ----
    mlp_head<<<GG, 64>>>(fc1w, fc1b, fc2w, fc2b, out);
}

// round 16
// speedup vs baseline: 1.1015x; 1.1015x over previous
#include <cuda_runtime.h>
#include <cuda_fp16.h>
#include <math.h>
#include <stdint.h>

#define NN   50000
#define EE   400000
#define ET   (EE + NN)
#define F    256
#define HH   4
#define CC   64
#define GG   64
#define NCLS 10

// ---------------- scratch (static device globals; no allocations) -----------
__device__ __align__(16) __half g_hh[(size_t)NN * F];    // h = A' @ W, fp16
__device__ __align__(16) __half g_y1h[(size_t)NN * F];   // layer-1 output, fp16
__device__ float g_asrc[NN * HH];
__device__ float g_adst[NN * HH];
__device__ float g_sum[F], g_sumsq[F];
__device__ float g_sc1[F], g_sh1[F];
__device__ float g_sc2[F], g_sh2[F];
__device__ float g_pool[GG * F];
__device__ float g_cnt[GG];
__device__ __align__(16) __half g_Bp[256 * 256];   // fp16 W
// CSR
__device__ int   g_cnt_n[NN];
__device__ int   g_rp[NN + 1];
__device__ int   g_col[ET];
#define SCAN_NB ((NN + 255) / 256)
__device__ int   g_blk[256];

// ---------------- helpers -----------------------------------------------------
__device__ __forceinline__ uint32_t pack_h2(float a, float b) {
    __half2 h = __floats2half2_rn(a, b);
    return *(uint32_t*)&h;
}
__device__ __forceinline__ void red4(float* p, float a, float b, float c, float d) {
    asm volatile("red.global.add.v4.f32 [%0], {%1,%2,%3,%4};"
                 :: "l"(p), "f"(a), "f"(b), "f"(c), "f"(d) : "memory");
}

// ---- conv_B: W[256][256] fp32 -> fp16 ---------------------------------------
__global__ void conv_B(const float* __restrict__ W) {
    int k = blockIdx.x, n = threadIdx.x;
    g_Bp[(size_t)k * 256 + n] = __float2half_rn(W[k * 256 + n]);
}

// ============ fp16 mma.sync GEMM, K=256, inline convert, fused attn ==========
#define PA 80
#define PB 272
#define ABUF (128 * PA)
#define BBUF (32 * PB)
#define STG  (ABUF + BBUF)

__device__ __forceinline__ uint32_t smem_u32(const void* p) {
    uint32_t a;
    asm("{ .reg .u64 t; cvta.to.shared.u64 t, %1; cvt.u32.u64 %0, t; }"
        : "=r"(a) : "l"(p));
    return a;
}
__device__ __forceinline__ void ldsm_x4(uint32_t* a, uint32_t addr) {
    asm volatile("ldmatrix.sync.aligned.m8n8.x4.shared.b16 {%0,%1,%2,%3}, [%4];"
                 : "=r"(a[0]), "=r"(a[1]), "=r"(a[2]), "=r"(a[3]) : "r"(addr));
}
__device__ __forceinline__ void ldsm_x2t(uint32_t* b, uint32_t addr) {
    asm volatile("ldmatrix.sync.aligned.m8n8.x2.trans.shared.b16 {%0,%1}, [%2];"
                 : "=r"(b[0]), "=r"(b[1]) : "r"(addr));
}
__device__ __forceinline__ void mma16816(float* d, const uint32_t* a,
                                         const uint32_t* b) {
    asm volatile(
        "mma.sync.aligned.m16n8k16.row.col.f32.f16.f16.f32 "
        "{%0,%1,%2,%3}, {%4,%5,%6,%7}, {%8,%9}, {%0,%1,%2,%3};"
        : "+f"(d[0]), "+f"(d[1]), "+f"(d[2]), "+f"(d[3])
        : "r"(a[0]), "r"(a[1]), "r"(a[2]), "r"(a[3]), "r"(b[0]), "r"(b[1]));
}
__device__ __forceinline__ void load_conv(const float* agp32, const __half* agp16,
                                          int kbase,
                                          const float* scale, const float* shift,
                                          bool ok, int sidx, uint32_t* hp) {
    float e[16];
    if (ok) {
        if (agp16) {
            uint4 v0 = *(const uint4*)(agp16 + kbase);
            uint4 v1 = *(const uint4*)(agp16 + kbase + 8);
            uint32_t u[4] = {v0.x, v0.y, v0.z, v0.w};
            uint32_t w[4] = {v1.x, v1.y, v1.z, v1.w};
#pragma unroll
            for (int i = 0; i < 4; i++) {
                float2 f = __half22float2(*(__half2*)&u[i]);
                e[i * 2 + 0] = f.x; e[i * 2 + 1] = f.y;
                float2 g = __half22float2(*(__half2*)&w[i]);
                e[8 + i * 2 + 0] = g.x; e[8 + i * 2 + 1] = g.y;
            }
        } else {
#pragma unroll
            for (int i = 0; i < 4; i++) {
                float4 v = *(const float4*)(agp32 + kbase + i * 4);
                e[i * 4 + 0] = v.x; e[i * 4 + 1] = v.y;
                e[i * 4 + 2] = v.z; e[i * 4 + 3] = v.w;
            }
        }
        if (scale) {
#pragma unroll
            for (int i = 0; i < 16; i++)
                e[i] = e[i] * scale[sidx + i] + shift[sidx + i];
        }
    } else {
#pragma unroll
        for (int i = 0; i < 16; i++) e[i] = 0.f;
    }
#pragma unroll
    for (int p = 0; p < 8; p++) hp[p] = pack_h2(e[2 * p], e[2 * p + 1]);
}

__global__ __launch_bounds__(256, 2)
void gemm_fp16(const float* __restrict__ A, const __half* __restrict__ A16,
               __half* __restrict__ C, int M,
               const float* __restrict__ scale, const float* __restrict__ shift,
               const float* __restrict__ atts, const float* __restrict__ attd) {
    __shared__ __align__(16) char sm[2 * STG];
    const int t = threadIdx.x, lane = t & 31, w = t >> 5;
    const int wm = w & 1, wn = w >> 1;
    const int row0 = blockIdx.x * 128, col0 = blockIdx.y * 128;
    const uint32_t sb = smem_u32(sm);

    float acc[4][4][4];
#pragma unroll
    for (int i = 0; i < 4; i++)
#pragma unroll
        for (int j = 0; j < 4; j++)
#pragma unroll
            for (int k = 0; k < 4; k++) acc[i][j][k] = 0.f;

    const int ar = t >> 1, apart = t & 1;
    const bool a_ok = (row0 + ar) < M;
    const float* agp32 = A   ? A   + (size_t)(row0 + ar) * 256 + apart * 16 : NULL;
    const __half* agp16 = A16 ? A16 + (size_t)(row0 + ar) * 256 + apart * 16 : NULL;
    const int br = t >> 3, bseg = t & 7;
    const __half* bgp = g_Bp + (size_t)br * 256 + col0 + bseg * 16;

    uint32_t hp[8];

    load_conv(agp32, agp16, 0, scale, shift, a_ok, apart * 16, hp);
    {
        char* pa = sm + ar * PA + apart * 32;
        *(uint4*)pa = *(uint4*)&hp[0];
        *(uint4*)(pa + 16) = *(uint4*)&hp[4];
        uint4 lb0 = *(const uint4*)(bgp);
        uint4 lb1 = *(const uint4*)(bgp + 8);
        char* pb = sm + ABUF + br * PB + bseg * 32;
        *(uint4*)pb = lb0; *(uint4*)(pb + 16) = lb1;
    }
    __syncthreads();

    for (int s = 0; s < 8; s++) {
        const int buf = s & 1;
        const uint32_t sba = sb + buf * STG;
        const int sn = s + 1;
        uint4 lb0, lb1;
        if (s < 7) {
            lb0 = *(const uint4*)(bgp + (size_t)(sn * 32) * 256);
            lb1 = *(const uint4*)(bgp + (size_t)(sn * 32) * 256 + 8);
            load_conv(agp32, agp16, sn * 32, scale, shift, a_ok,
                      sn * 32 + apart * 16, hp);
        }
#pragma unroll
        for (int kh = 0; kh < 2; kh++) {
            uint32_t afr[4][4], bfr[4][2];
#pragma unroll
            for (int mi = 0; mi < 4; mi++) {
                uint32_t addr = sba + (uint32_t)(wm * 64 + mi * 16 + (lane & 15)) * PA
                              + kh * 32 + (lane >> 4) * 16;
                ldsm_x4(afr[mi], addr);
            }
#pragma unroll
            for (int nf = 0; nf < 4; nf++) {
                uint32_t addr = sba + ABUF + (uint32_t)(kh * 16 + (lane & 15)) * PB
                              + (wn * 32 + nf * 8) * 2;
                ldsm_x2t(bfr[nf], addr);
            }
#pragma unroll
            for (int mi = 0; mi < 4; mi++)
#pragma unroll
                for (int nf = 0; nf < 4; nf++)
                    mma16816(acc[mi][nf], afr[mi], bfr[nf]);
        }
        if (s < 7) {
            char* base = sm + (buf ^ 1) * STG;
            char* pb = base + ABUF + br * PB + bseg * 32;
            *(uint4*)pb = lb0; *(uint4*)(pb + 16) = lb1;
            char* pa = base + ar * PA + apart * 32;
            *(uint4*)pa = *(uint4*)&hp[0];
            *(uint4*)(pa + 16) = *(uint4*)&hp[4];
        }
        __syncthreads();
    }

    // ---- epilogue: store C (fp16), per-warp att partials -> smem, combine ---
    float* part = (float*)sm;
#pragma unroll
    for (int mi = 0; mi < 4; mi++) {
        int lr_lo = wm * 64 + mi * 16 + (lane >> 2);
        int lr_hi = lr_lo + 8;
        int r_lo = row0 + lr_lo, r_hi = row0 + lr_hi;
        float ds0 = 0.f, dd0 = 0.f, ds1 = 0.f, dd1 = 0.f;
#pragma unroll
        for (int nf = 0; nf < 4; nf++) {
            int c = col0 + wn * 32 + nf * 8 + (lane & 3) * 2;
            float v0 = acc[mi][nf][0], v1 = acc[mi][nf][1];
            float v2 = acc[mi][nf][2], v3 = acc[mi][nf][3];
            if (r_lo < M) *(__half2*)(C + (size_t)r_lo * 256 + c) = __floats2half2_rn(v0, v1);
            if (r_hi < M) *(__half2*)(C + (size_t)r_hi * 256 + c) = __floats2half2_rn(v2, v3);
            float s0 = atts[c], s1 = atts[c + 1];
            float d0 = attd[c], d1 = attd[c + 1];
            ds0 += v0 * s0 + v1 * s1; dd0 += v0 * d0 + v1 * d1;
            ds1 += v2 * s0 + v3 * s1; dd1 += v2 * d0 + v3 * d1;
        }
#pragma unroll
        for (int o = 1; o <= 2; o <<= 1) {
            ds0 += __shfl_xor_sync(0xFFFFFFFFu, ds0, o);
            dd0 += __shfl_xor_sync(0xFFFFFFFFu, dd0, o);
            ds1 += __shfl_xor_sync(0xFFFFFFFFu, ds1, o);
            dd1 += __shfl_xor_sync(0xFFFFFFFFu, dd1, o);
        }
        if ((lane & 3) == 0) {
            part[(lr_lo * 4 + wn) * 2 + 0] = ds0;
            part[(lr_lo * 4 + wn) * 2 + 1] = dd0;
            part[(lr_hi * 4 + wn) * 2 + 0] = ds1;
            part[(lr_hi * 4 + wn) * 2 + 1] = dd1;
        }
    }
    __syncthreads();
    {
        int lr = t & 127, sd = t >> 7;
        int gr = row0 + lr;
        if (gr < M) {
            float* dst = sd ? g_adst : g_asrc;
#pragma unroll
            for (int hl = 0; hl < 2; hl++) {
                float v = part[(lr * 4 + 2 * hl) * 2 + sd]
                        + part[(lr * 4 + 2 * hl + 1) * 2 + sd];
                dst[gr * HH + (col0 >> 6) + hl] = v;
            }
        }
    }
}

// ------------------------------ CSR build -----------------------------------
__global__ void csr_zero() {
    int i = blockIdx.x * blockDim.x + threadIdx.x;
    if (i < NN) g_cnt_n[i] = 0;
    if (i < F)  { g_sum[i] = 0.f; g_sumsq[i] = 0.f; }
    if (i < GG * F) g_pool[i] = 0.f;
    if (i < GG) g_cnt[i] = 0.f;
}
__global__ void csr_hist(const int* __restrict__ ei) {
    int e = blockIdx.x * blockDim.x + threadIdx.x;
    if (e >= ET) return;
    int d = (e < EE) ? ei[EE + e] : e - EE;
    atomicAdd(&g_cnt_n[d], 1);
}
__global__ void cnt_hist(const int* __restrict__ bt) {
    __shared__ int hcnt[GG];
    int t = threadIdx.x;
    if (t < GG) hcnt[t] = 0;
    __syncthreads();
    int i = blockIdx.x * blockDim.x + t;
    if (i < NN) atomicAdd(&hcnt[bt[i]], 1);
    __syncthreads();
    if (t < GG && hcnt[t]) atomicAdd(&g_cnt[t], (float)hcnt[t]);
}
__global__ void scan_p1() {
    __shared__ int ps[256];
    int t = threadIdx.x, i = blockIdx.x * 256 + t;
    int v = (i < NN) ? g_cnt_n[i] : 0;
    ps[t] = v;
    __syncthreads();
#pragma unroll
    for (int off = 128; off; off >>= 1) {
        if (t < off) ps[t] += ps[t + off];
        __syncthreads();
    }
    if (t == 0) g_blk[blockIdx.x] = ps[0];
}
__global__ void scan_p2() {
    __shared__ int ps[256];
    int t = threadIdx.x;
    ps[t] = (t < SCAN_NB) ? g_blk[t] : 0;
    __syncthreads();
#pragma unroll
    for (int off = 1; off < 256; off <<= 1) {
        int v = (t >= off) ? ps[t - off] : 0;
        __syncthreads();
        ps[t] += v;
        __syncthreads();
    }
    g_blk[t] = ps[t];
}
__global__ void scan_p3() {
    __shared__ int ps[256];
    int t = threadIdx.x, b = blockIdx.x, i = b * 256 + t;
    int v = (i < NN) ? g_cnt_n[i] : 0;
    ps[t] = v;
    __syncthreads();
#pragma unroll
    for (int off = 1; off < 256; off <<= 1) {
        int u = (t >= off) ? ps[t - off] : 0;
        __syncthreads();
        ps[t] += u;
        __syncthreads();
    }
    int base = b ? g_blk[b - 1] : 0;
    int excl = base + ps[t] - v;
    if (i < NN) {
        g_rp[i] = excl;
        g_cnt_n[i] = excl;
        if (i == NN - 1) g_rp[NN] = excl + v;
    }
}
__global__ void csr_scatter(const int* __restrict__ ei) {
    int e = blockIdx.x * blockDim.x + threadIdx.x;
    if (e >= ET) return;
    int s, d;
    if (e < EE) { s = ei[e]; d = ei[EE + e]; }
    else        { s = d = e - EE; }
    int pos = atomicAdd(&g_cnt_n[d], 1);
    g_col[pos] = s;
}

// ----- fused GAT aggregate + bias + ELU + residual(+BN) + BN stats -----------
// Warp per (dst, 128-col half); edge loop 8/4/1 pipelined. RPW=2 for balance.
#define RPW 2
__global__ __launch_bounds__(256)
void gat_agg(const float* __restrict__ b,
             const float* __restrict__ xin32,
             const __half* __restrict__ xin16,
             const float* __restrict__ rscale,
             const float* __restrict__ rshift,
             __half* __restrict__ y16,
             const int* __restrict__ bat, int do_pool) {
    __shared__ float bsum[F], bsq[F];
    int t = threadIdx.x;
    bsum[t] = 0.f; bsq[t] = 0.f;
    __syncthreads();

    int lane = t & 31;
    int gwarp = blockIdx.x * 8 + (t >> 5);
    int hf = gwarp & 1;
    int d0 = (gwarp >> 1) * RPW;
    int c = hf * 128 + (lane << 2);
    int h = hf * 2 + (lane >> 4);

    float4 bias = *(const float4*)(b + c);
    float scv = rscale ? rscale[c] : 1.f,     shv = rshift ? rshift[c] : 0.f;
    float scy = rscale ? rscale[c + 1] : 1.f, shy = rshift ? rshift[c + 1] : 0.f;
    float scz = rscale ? rscale[c + 2] : 1.f, shz = rshift ? rshift[c + 2] : 0.f;
    float scw = rscale ? rscale[c + 3] : 1.f, shw = rshift ? rshift[c + 3] : 0.f;

    float ss[4] = {0, 0, 0, 0};
    float sq[4] = {0, 0, 0, 0};
    float pa[4] = {0, 0, 0, 0};
    int curg = -1;

#pragma unroll
    for (int rr = 0; rr < RPW; rr++) {
        int d = d0 + rr;
        if (d >= NN) break;
        float ad = g_adst[d * HH + h];
        float ax = 0.f, ay = 0.f, az = 0.f, aw = 0.f;
        float den = 0.f;
        int e0 = g_rp[d], e1 = g_rp[d + 1];
        int e = e0;
        // 8-wide pipelined leg (MLP ~16)
        for (; e + 8 <= e1; e += 8) {
            int sid[8];
#pragma unroll
            for (int j = 0; j < 8; j++) sid[j] = g_col[e + j];
            float av[8];
            uint2 uv[8];
#pragma unroll
            for (int j = 0; j < 8; j++) av[j] = g_asrc[sid[j] * HH + h];
#pragma unroll
            for (int j = 0; j < 8; j++)
                uv[j] = *(const uint2*)(g_hh + (size_t)sid[j] * F + c);
#pragma unroll
            for (int j = 0; j < 8; j++) {
                float v = av[j] + ad;
                v = v > 0.f ? v : 0.2f * v;
                float ex = __expf(v);
                den += ex;
                float2 f0 = __half22float2(*(__half2*)&uv[j].x);
                float2 f1 = __half22float2(*(__half2*)&uv[j].y);
                ax += ex * f0.x; ay += ex * f0.y;
                az += ex * f1.x; aw += ex * f1.y;
            }
        }
        // 4-wide leg
        for (; e + 4 <= e1; e += 4) {
            int s0 = g_col[e], s1 = g_col[e + 1];
            int s2 = g_col[e + 2], s3 = g_col[e + 3];
            float a0 = g_asrc[s0 * HH + h], a1 = g_asrc[s1 * HH + h];
            float a2 = g_asrc[s2 * HH + h], a3 = g_asrc[s3 * HH + h];
            uint2 u0 = *(const uint2*)(g_hh + (size_t)s0 * F + c);
            uint2 u1 = *(const uint2*)(g_hh + (size_t)s1 * F + c);
            uint2 u2 = *(const uint2*)(g_hh + (size_t)s2 * F + c);
            uint2 u3 = *(const uint2*)(g_hh + (size_t)s3 * F + c);
            float v0 = a0 + ad, v1 = a1 + ad, v2 = a2 + ad, v3 = a3 + ad;
            v0 = v0 > 0.f ? v0 : 0.2f * v0;
            v1 = v1 > 0.f ? v1 : 0.2f * v1;
            v2 = v2 > 0.f ? v2 : 0.2f * v2;
            v3 = v3 > 0.f ? v3 : 0.2f * v3;
            float x0 = __expf(v0), x1 = __expf(v1);
            float x2 = __expf(v2), x3 = __expf(v3);
            den += (x0 + x1) + (x2 + x3);
            float2 p0 = __half22float2(*(__half2*)&u0.x);
            float2 q0 = __half22float2(*(__half2*)&u0.y);
            float2 p1 = __half22float2(*(__half2*)&u1.x);
            float2 q1 = __half22float2(*(__half2*)&u1.y);
            float2 p2 = __half22float2(*(__half2*)&u2.x);
            float2 q2 = __half22float2(*(__half2*)&u2.y);
            float2 p3 = __half22float2(*(__half2*)&u3.x);
            float2 q3 = __half22float2(*(__half2*)&u3.y);
            ax += x0 * p0.x + x1 * p1.x + x2 * p2.x + x3 * p3.x;
            ay += x0 * p0.y + x1 * p1.y + x2 * p2.y + x3 * p3.y;
            az += x0 * q0.x + x1 * q1.x + x2 * q2.x + x3 * q3.x;
            aw += x0 * q0.y + x1 * q1.y + x2 * q2.y + x3 * q3.y;
        }
        for (; e < e1; e++) {
            int s = g_col[e];
            float v = g_asrc[s * HH + h] + ad;
            v = v > 0.f ? v : 0.2f * v;
            float ex = __expf(v);
            den += ex;
            uint2 u = *(const uint2*)(g_hh + (size_t)s * F + c);
            float2 f0 = __half22float2(*(__half2*)&u.x);
            float2 f1 = __half22float2(*(__half2*)&u.y);
            ax += ex * f0.x; ay += ex * f0.y;
            az += ex * f1.x; aw += ex * f1.y;
        }
        float inv = __fdividef(1.f, den);
        float xv[4];
        if (xin16) {
            uint2 u = *(const uint2*)(xin16 + (size_t)d * F + c);
            float2 f0 = __half22float2(*(__half2*)&u.x);
            float2 f1 = __half22float2(*(__half2*)&u.y);
            xv[0] = f0.x; xv[1] = f0.y; xv[2] = f1.x; xv[3] = f1.y;
        } else {
            float4 xr = *(const float4*)(xin32 + (size_t)d * F + c);
            xv[0] = xr.x; xv[1] = xr.y; xv[2] = xr.z; xv[3] = xr.w;
        }
        float o[4];
        o[0] = ax * inv + bias.x; o[1] = ay * inv + bias.y;
        o[2] = az * inv + bias.z; o[3] = aw * inv + bias.w;
#pragma unroll
        for (int j = 0; j < 4; j++) o[j] = o[j] > 0.f ? o[j] : expm1f(o[j]);
        o[0] += xv[0] * scv + shv; o[1] += xv[1] * scy + shy;
        o[2] += xv[2] * scz + shz; o[3] += xv[3] * scw + shw;
        if (do_pool) {
            int gb = bat[d];
            if (gb != curg) {
                if (curg >= 0)
                    red4(&g_pool[curg * F + c], pa[0], pa[1], pa[2], pa[3]);
                curg = gb;
                pa[0] = pa[1] = pa[2] = pa[3] = 0.f;
            }
#pragma unroll
            for (int j = 0; j < 4; j++) pa[j] += o[j];
        } else {
            __half2 h0 = __floats2half2_rn(o[0], o[1]);
            __half2 h1 = __floats2half2_rn(o[2], o[3]);
            uint2 uo;
            uo.x = *(uint32_t*)&h0; uo.y = *(uint32_t*)&h1;
            *(uint2*)(y16 + (size_t)d * F + c) = uo;
        }
#pragma unroll
        for (int j = 0; j < 4; j++) { ss[j] += o[j]; sq[j] += o[j] * o[j]; }
    }
    if (do_pool && curg >= 0)
        red4(&g_pool[curg * F + c], pa[0], pa[1], pa[2], pa[3]);
#pragma unroll
    for (int j = 0; j < 4; j++) {
        atomicAdd(&bsum[c + j], ss[j]);
        atomicAdd(&bsq[c + j],  sq[j]);
    }
    __syncthreads();
    atomicAdd(&g_sum[t],   bsum[t]);
    atomicAdd(&g_sumsq[t], bsq[t]);
}

__global__ void bn_final(const float* __restrict__ gm, const float* __restrict__ bt,
                         float* __restrict__ sc_out, float* __restrict__ sh_out) {
    int f = threadIdx.x;
    float mu  = g_sum[f] / (float)NN;
    float var = g_sumsq[f] / (float)NN - mu * mu;
    float sc  = gm[f] * rsqrtf(var + 1e-5f);
    sc_out[f] = sc;
    sh_out[f] = bt[f] - mu * sc;
    g_sum[f] = 0.f; g_sumsq[f] = 0.f;
}

// ---------- MLP head: BN2 affine on pooled raw sums + log softmax ------------
__global__ void mlp_head(const float* __restrict__ fc1w, const float* __restrict__ fc1b,
                         const float* __restrict__ fc2w, const float* __restrict__ fc2b,
                         float* __restrict__ out) {
    __shared__ float p[F];
    __shared__ float z[CC];
    __shared__ float l[NCLS];
    __shared__ float red[2];
    int g = blockIdx.x;
    int t = threadIdx.x;
    float cnt = fmaxf(g_cnt[g], 1.f);
    float inv = 1.f / cnt;
    for (int k = t; k < F; k += 64)
        p[k] = (g_sc2[k] * g_pool[g * F + k] + g_sh2[k] * cnt) * inv;
    __syncthreads();
    float acc = fc1b[t];
    for (int k = 0; k < F; k++) acc += p[k] * fc1w[k * CC + t];
    z[t] = fmaxf(acc, 0.f);
    __syncthreads();
    if (t < NCLS) {
        float a = fc2b[t];
        for (int k = 0; k < CC; k++) a += z[k] * fc2w[k * NCLS + t];
        l[t] = a;
    }
    __syncthreads();
    if (t == 0) {
        float m = l[0];
        for (int i = 1; i < NCLS; i++) m = fmaxf(m, l[i]);
        float s = 0.f;
        for (int i = 0; i < NCLS; i++) s += expf(l[i] - m);
        red[0] = m; red[1] = logf(s);
    }
    __syncthreads();
    if (t < NCLS) out[g * NCLS + t] = l[t] - red[0] - red[1];
}

// ---------------------------------- launch ----------------------------------
extern "C" void kernel_launch(void* const* d_in, const int* in_sizes, int n_in,
                              void* d_out, int out_size) {
    const float* x    = (const float*)d_in[0];
    const int*   ei   = (const int*)  d_in[1];
    const int*   bat  = (const int*)  d_in[2];
    const float* W1   = (const float*)d_in[3];
    const float* as1  = (const float*)d_in[4];
    const float* ad1  = (const float*)d_in[5];
    const float* b1   = (const float*)d_in[6];
    const float* gm1  = (const float*)d_in[7];
    const float* be1  = (const float*)d_in[8];
    const float* W2   = (const float*)d_in[9];
    const float* as2  = (const float*)d_in[10];
    const float* ad2  = (const float*)d_in[11];
    const float* b2   = (const float*)d_in[12];
    const float* gm2  = (const float*)d_in[13];
    const float* be2  = (const float*)d_in[14];
    const float* fc1w = (const float*)d_in[15];
    const float* fc1b = (const float*)d_in[16];
    const float* fc2w = (const float*)d_in[17];
    const float* fc2b = (const float*)d_in[18];
    float* out = (float*)d_out;

    __half *phh, *py1h;
    float *psc1, *psh1, *psc2, *psh2;
    cudaGetSymbolAddress((void**)&phh,  g_hh);
    cudaGetSymbolAddress((void**)&py1h, g_y1h);
    cudaGetSymbolAddress((void**)&psc1, g_sc1);
    cudaGetSymbolAddress((void**)&psh1, g_sh1);
    cudaGetSymbolAddress((void**)&psc2, g_sc2);
    cudaGetSymbolAddress((void**)&psh2, g_sh2);

    static cudaStream_t s2 = nullptr;
    static cudaEvent_t evFork = nullptr, evCsr = nullptr,
                       evGemm1 = nullptr, evConvB2 = nullptr;
    if (!s2) {
        cudaStreamCreateWithFlags(&s2, cudaStreamNonBlocking);
        cudaEventCreateWithFlags(&evFork,   cudaEventDisableTiming);
        cudaEventCreateWithFlags(&evCsr,    cudaEventDisableTiming);
        cudaEventCreateWithFlags(&evGemm1,  cudaEventDisableTiming);
        cudaEventCreateWithFlags(&evConvB2, cudaEventDisableTiming);
    }

    const int TPB = 256;
    const int nET = (ET + TPB - 1) / TPB;
    const int nNN = (NN + TPB - 1) / TPB;
    dim3 mmGrid((NN + 127) / 128, 2);
    const int nAGG  = (2 * NN + 8 * RPW - 1) / (8 * RPW);
    const int nZERO = (GG * F + TPB - 1) / TPB > nNN
                      ? (GG * F + TPB - 1) / TPB : nNN;

    // ---- fork: CSR build chain on side stream, GEMM path on main -----------
    cudaEventRecord(evFork, 0);
    cudaStreamWaitEvent(s2, evFork, 0);

    csr_zero<<<nZERO, TPB, 0, s2>>>();
    csr_hist<<<nET, TPB, 0, s2>>>(ei);
    cnt_hist<<<nNN, TPB, 0, s2>>>(bat);
    scan_p1<<<SCAN_NB, 256, 0, s2>>>();
    scan_p2<<<1, 256, 0, s2>>>();
    scan_p3<<<SCAN_NB, 256, 0, s2>>>();
    csr_scatter<<<nET, TPB, 0, s2>>>(ei);
    cudaEventRecord(evCsr, s2);

    // main: layer-1 GEMM (independent of CSR)
    conv_B<<<256, 256>>>(W1);
    gemm_fp16<<<mmGrid, 256>>>(x, NULL, phh, NN, NULL, NULL, as1, ad1);
    cudaEventRecord(evGemm1, 0);

    // side: conv_B(W2) after gemm1 released g_Bp, overlapping gat_agg1
    cudaStreamWaitEvent(s2, evGemm1, 0);
    conv_B<<<256, 256, 0, s2>>>(W2);
    cudaEventRecord(evConvB2, s2);

    // main: join CSR, run layer-1 aggregation (writes y1 fp16)
    cudaStreamWaitEvent(0, evCsr, 0);
    gat_agg<<<nAGG, 256>>>(b1, x, NULL, NULL, NULL, py1h, bat, 0);
    bn_final<<<1, F>>>(gm1, be1, psc1, psh1);

    // main: join conv_B(W2), layer 2 (A from fp16 y1, pooling fused)
    cudaStreamWaitEvent(0, evConvB2, 0);
    gemm_fp16<<<mmGrid, 256>>>(NULL, py1h, phh, NN, psc1, psh1, as2, ad2);
    gat_agg<<<nAGG, 256>>>(b2, NULL, py1h, psc1, psh1, NULL, bat, 1);
    bn_final<<<1, F>>>(gm2, be2, psc2, psh2);

    // ---- head ----
    mlp_head<<<GG, 64>>>(fc1w, fc1b, fc2w, fc2b, out);
}